// round 2
// baseline (speedup 1.0000x reference)
#include <cuda_runtime.h>

// QNN: 4-qubit RY/CNOT circuit + linear head + softmax.
// 2 samples per thread, packed into f32x2 (Blackwell FFMA2 path).
// Inputs: x [B,4] f32, quantum_weights [3,4] f32, W [6,4] f32, b [6] f32.
// Output: softmax probs [B,6] f32.

#define NQ 4
#define DIM 16

typedef unsigned long long f2_t;  // two packed f32 (lo = sample A, hi = sample B)

__device__ __forceinline__ f2_t pk(float lo, float hi) {
    f2_t r; asm("mov.b64 %0, {%1,%2};" : "=l"(r) : "f"(lo), "f"(hi)); return r;
}
__device__ __forceinline__ void upk(f2_t v, float& lo, float& hi) {
    asm("mov.b64 {%0,%1}, %2;" : "=f"(lo), "=f"(hi) : "l"(v));
}
__device__ __forceinline__ f2_t mul2(f2_t a, f2_t b) {
    f2_t r; asm("mul.rn.f32x2 %0, %1, %2;" : "=l"(r) : "l"(a), "l"(b)); return r;
}
__device__ __forceinline__ f2_t add2(f2_t a, f2_t b) {
    f2_t r; asm("add.rn.f32x2 %0, %1, %2;" : "=l"(r) : "l"(a), "l"(b)); return r;
}
__device__ __forceinline__ f2_t fma2(f2_t a, f2_t b, f2_t c) {
    f2_t r; asm("fma.rn.f32x2 %0, %1, %2, %3;" : "=l"(r) : "l"(a), "l"(b), "l"(c)); return r;
}

__global__ __launch_bounds__(256) void qnn_kernel(
    const float4* __restrict__ x,     // [B] rows of 4 angles
    const float*  __restrict__ qw,    // [12] trainable angles
    const float*  __restrict__ W,     // [24] = [6,4]
    const float*  __restrict__ bias,  // [6]
    float2*       __restrict__ out,   // [B*3] (== [B,6] f32)
    int B)
{
    __shared__ f2_t cw2[12], sw2[12], nsw2[12];  // packed (c,c), (s,s), (-s,-s)
    __shared__ f2_t W2[24], b2[6];

    int t = threadIdx.x;
    if (t < 12) {
        float s, c; __sincosf(0.5f * qw[t], &s, &c);
        cw2[t] = pk(c, c); sw2[t] = pk(s, s); nsw2[t] = pk(-s, -s);
    }
    if (t < 24) { float w = W[t]; W2[t] = pk(w, w); }
    if (t < 6)  { float v = bias[t]; b2[t] = pk(v, v); }
    __syncthreads();

    int base = blockIdx.x * 512;
    int iA = base + t;
    int iB = iA + 256;
    bool vA = iA < B, vB = iB < B;

    float4 xA = vA ? x[iA] : make_float4(0.f, 0.f, 0.f, 0.f);
    float4 xB = vB ? x[iB] : make_float4(0.f, 0.f, 0.f, 0.f);

    // ---- encoding: sincos per sample (scalar MUFU), then pack
    float cA[4], sA[4], cB[4], sB[4];
    __sincosf(0.5f * xA.x, &sA[0], &cA[0]);
    __sincosf(0.5f * xA.y, &sA[1], &cA[1]);
    __sincosf(0.5f * xA.z, &sA[2], &cA[2]);
    __sincosf(0.5f * xA.w, &sA[3], &cA[3]);
    __sincosf(0.5f * xB.x, &sB[0], &cB[0]);
    __sincosf(0.5f * xB.y, &sB[1], &cB[1]);
    __sincosf(0.5f * xB.z, &sB[2], &cB[2]);
    __sincosf(0.5f * xB.w, &sB[3], &cB[3]);

    f2_t c0 = pk(cA[0], cB[0]), s0 = pk(sA[0], sB[0]);
    f2_t c1 = pk(cA[1], cB[1]), s1 = pk(sA[1], sB[1]);
    f2_t c2 = pk(cA[2], cB[2]), s2 = pk(sA[2], sB[2]);
    f2_t c3 = pk(cA[3], cB[3]), s3 = pk(sA[3], sB[3]);

    // |psi> = RY(x0)|0> x RY(x1)|0> x RY(x2)|0> x RY(x3)|0>
    // bit for qubit q is (idx >> (3-q)) & 1 (wire 0 most significant)
    f2_t p01[4], p23[4];
    p01[0] = mul2(c0, c1); p01[1] = mul2(c0, s1); p01[2] = mul2(s0, c1); p01[3] = mul2(s0, s1);
    p23[0] = mul2(c2, c3); p23[1] = mul2(c2, s3); p23[2] = mul2(s2, c3); p23[3] = mul2(s2, s3);

    f2_t st[DIM];
    #pragma unroll
    for (int a = 0; a < 4; a++)
        #pragma unroll
        for (int d = 0; d < 4; d++)
            st[a * 4 + d] = mul2(p01[a], p23[d]);

    // ---- 3 layers trainable RYs; ring CNOTs after layers 0,1
    #pragma unroll
    for (int layer = 0; layer < 3; layer++) {
        #pragma unroll
        for (int q = 0; q < NQ; q++) {
            f2_t cc = cw2[layer * 4 + q];
            f2_t ss = sw2[layer * 4 + q];
            f2_t ns = nsw2[layer * 4 + q];
            const int mask = 1 << (3 - q);
            #pragma unroll
            for (int idx = 0; idx < DIM; idx++) {
                if ((idx & mask) == 0) {
                    f2_t a0 = st[idx];
                    f2_t a1 = st[idx | mask];
                    st[idx]        = fma2(ns, a1, mul2(cc, a0));
                    st[idx | mask] = fma2(cc, a1, mul2(ss, a0));
                }
            }
        }
        if (layer < 2) {
            // ring CNOTs (0,1),(1,2),(2,3),(3,0): compile-time register swaps
            #pragma unroll
            for (int e = 0; e < NQ; e++) {
                const int mc = 1 << (3 - e);
                const int mt = 1 << (3 - ((e + 1) & 3));
                #pragma unroll
                for (int idx = 0; idx < DIM; idx++) {
                    if ((idx & mc) && !(idx & mt)) {
                        f2_t tmp = st[idx];
                        st[idx] = st[idx | mt];
                        st[idx | mt] = tmp;
                    }
                }
            }
        }
    }

    // ---- probabilities
    f2_t p[DIM];
    #pragma unroll
    for (int idx = 0; idx < DIM; idx++) p[idx] = mul2(st[idx], st[idx]);

    // ---- Z readout via shared partial-sum tree
    // e[j] = p[2j]+p[2j+1], d[j] = p[2j]-p[2j+1]  (pair over qubit 3)
    const f2_t NEG1 = pk(-1.f, -1.f);
    f2_t e[8], d[8];
    #pragma unroll
    for (int j = 0; j < 8; j++) {
        e[j] = add2(p[2 * j], p[2 * j + 1]);
        d[j] = fma2(NEG1, p[2 * j + 1], p[2 * j]);
    }
    f2_t z3 = add2(add2(add2(d[0], d[1]), add2(d[2], d[3])),
                   add2(add2(d[4], d[5]), add2(d[6], d[7])));
    f2_t f[4], g[4];
    #pragma unroll
    for (int m = 0; m < 4; m++) {
        f[m] = add2(e[2 * m], e[2 * m + 1]);
        g[m] = fma2(NEG1, e[2 * m + 1], e[2 * m]);
    }
    f2_t z2 = add2(add2(g[0], g[1]), add2(g[2], g[3]));
    f2_t z1 = add2(fma2(NEG1, f[1], f[0]), fma2(NEG1, f[3], f[2]));
    f2_t z0 = fma2(NEG1, add2(f[2], f[3]), add2(f[0], f[1]));
    f2_t z[NQ] = {z0, z1, z2, z3};

    // ---- linear head (packed)
    f2_t l2[6];
    #pragma unroll
    for (int k = 0; k < 6; k++) {
        f2_t acc = b2[k];
        #pragma unroll
        for (int q = 0; q < NQ; q++) acc = fma2(W2[k * 4 + q], z[q], acc);
        l2[k] = acc;
    }

    // ---- softmax per sample (|logit| small; skip max-subtraction)
    float lA[6], lB[6];
    #pragma unroll
    for (int k = 0; k < 6; k++) upk(l2[k], lA[k], lB[k]);

    {
        float eo[6], ssum = 0.f;
        #pragma unroll
        for (int k = 0; k < 6; k++) { eo[k] = __expf(lA[k]); ssum += eo[k]; }
        float inv = __frcp_rn(ssum);
        if (vA) {
            out[iA * 3 + 0] = make_float2(eo[0] * inv, eo[1] * inv);
            out[iA * 3 + 1] = make_float2(eo[2] * inv, eo[3] * inv);
            out[iA * 3 + 2] = make_float2(eo[4] * inv, eo[5] * inv);
        }
    }
    {
        float eo[6], ssum = 0.f;
        #pragma unroll
        for (int k = 0; k < 6; k++) { eo[k] = __expf(lB[k]); ssum += eo[k]; }
        float inv = __frcp_rn(ssum);
        if (vB) {
            out[iB * 3 + 0] = make_float2(eo[0] * inv, eo[1] * inv);
            out[iB * 3 + 1] = make_float2(eo[2] * inv, eo[3] * inv);
            out[iB * 3 + 2] = make_float2(eo[4] * inv, eo[5] * inv);
        }
    }
}

extern "C" void kernel_launch(void* const* d_in, const int* in_sizes, int n_in,
                              void* d_out, int out_size) {
    const float4* x  = (const float4*)d_in[0];
    const float*  qw = (const float*)d_in[1];
    const float*  W  = (const float*)d_in[2];
    const float*  b  = (const float*)d_in[3];
    float2* out = (float2*)d_out;
    int B = in_sizes[0] / 4;
    int threads = 256;
    int samples_per_block = threads * 2;
    int blocks = (B + samples_per_block - 1) / samples_per_block;
    qnn_kernel<<<blocks, threads>>>(x, qw, W, b, out, B);
}

// round 3
// speedup vs baseline: 1.6400x; 1.6400x over previous
#include <cuda_runtime.h>

// QNN: 4-qubit RY/CNOT circuit + linear head + softmax. One sample per thread.
// Algebraic folds: layer-0 RYs merged into encoding angles (RY(a)RY(b)=RY(a+b));
// layer-2 RYs merged into Z-readout via R(t)^T Z R(t) = cos(t) Z - sin(t) X.
// Inputs: x [B,4] f32, quantum_weights [3,4] f32, W [6,4] f32, b [6] f32.
// Output: softmax probs [B,6] f32.

#define NQ 4
#define DIM 16

__global__ __launch_bounds__(256) void qnn_kernel(
    const float4* __restrict__ x,     // [B] rows of 4 angles
    const float*  __restrict__ qw,    // [12] trainable angles (3 layers x 4 qubits)
    const float*  __restrict__ W,     // [24] = [6,4]
    const float*  __restrict__ bias,  // [6]
    float2*       __restrict__ out,   // [B*3] (== [B,6] f32)
    int B)
{
    __shared__ float hw0[4];          // 0.5 * layer0 angle (folded into encoding)
    __shared__ float c1w[4], s1w[4];  // cos/sin of layer1 half-angles
    __shared__ float czw[4], nxw[4];  // cos(theta2), -2*sin(theta2) (full angle!)
    __shared__ float Ws[24], bs[6];

    int t = threadIdx.x;
    if (t < 4) {
        hw0[t] = 0.5f * qw[t];
        float s, c;
        __sincosf(0.5f * qw[4 + t], &s, &c);
        c1w[t] = c; s1w[t] = s;
        float s2, c2;
        __sincosf(qw[8 + t], &s2, &c2);     // FULL angle for the observable fold
        czw[t] = c2; nxw[t] = -2.0f * s2;
    }
    if (t < 24) Ws[t] = W[t];
    if (t < 6)  bs[t] = bias[t];
    __syncthreads();

    int i = blockIdx.x * 256 + t;
    if (i >= B) return;

    // ---- encoding + layer0: |psi> = prod_q RY(x_q + w0_q)|0>
    float4 xv = x[i];
    float ca[4], sa[4];
    __sincosf(fmaf(0.5f, xv.x, hw0[0]), &sa[0], &ca[0]);
    __sincosf(fmaf(0.5f, xv.y, hw0[1]), &sa[1], &ca[1]);
    __sincosf(fmaf(0.5f, xv.z, hw0[2]), &sa[2], &ca[2]);
    __sincosf(fmaf(0.5f, xv.w, hw0[3]), &sa[3], &ca[3]);

    // index bit for qubit q is (idx >> (3-q)) & 1 (wire 0 most significant)
    float p01[4], p23[4];
    p01[0] = ca[0] * ca[1]; p01[1] = ca[0] * sa[1];
    p01[2] = sa[0] * ca[1]; p01[3] = sa[0] * sa[1];
    p23[0] = ca[2] * ca[3]; p23[1] = ca[2] * sa[3];
    p23[2] = sa[2] * ca[3]; p23[3] = sa[2] * sa[3];

    float st[DIM];
    #pragma unroll
    for (int a = 0; a < 4; a++)
        #pragma unroll
        for (int d = 0; d < 4; d++)
            st[a * 4 + d] = p01[a] * p23[d];

    // ---- ring CNOTs #1 (register permutation, free)
    #pragma unroll
    for (int e = 0; e < NQ; e++) {
        const int mc = 1 << (3 - e);
        const int mt = 1 << (3 - ((e + 1) & 3));
        #pragma unroll
        for (int idx = 0; idx < DIM; idx++) {
            if ((idx & mc) && !(idx & mt)) {
                float tmp = st[idx]; st[idx] = st[idx | mt]; st[idx | mt] = tmp;
            }
        }
    }

    // ---- layer 1 trainable RYs (the only remaining butterfly layer)
    #pragma unroll
    for (int q = 0; q < NQ; q++) {
        float cc = c1w[q], ss = s1w[q];
        const int mask = 1 << (3 - q);
        #pragma unroll
        for (int idx = 0; idx < DIM; idx++) {
            if ((idx & mask) == 0) {
                float a0 = st[idx];
                float a1 = st[idx | mask];
                st[idx]        = fmaf(cc, a0, -ss * a1);
                st[idx | mask] = fmaf(ss, a0,  cc * a1);
            }
        }
    }

    // ---- ring CNOTs #2 (free)
    #pragma unroll
    for (int e = 0; e < NQ; e++) {
        const int mc = 1 << (3 - e);
        const int mt = 1 << (3 - ((e + 1) & 3));
        #pragma unroll
        for (int idx = 0; idx < DIM; idx++) {
            if ((idx & mc) && !(idx & mt)) {
                float tmp = st[idx]; st[idx] = st[idx | mt]; st[idx | mt] = tmp;
            }
        }
    }

    // ---- readout with layer 2 folded in:
    // z_q = cos(t_q) * <Z_q> - sin(t_q) * <X_q>,  <X_q> = 2 * sum_pairs a0*a1
    // <Z_q> via signed tree over probabilities
    float e_[8], d_[8];
    #pragma unroll
    for (int j = 0; j < 8; j++) {
        float q0 = st[2 * j] * st[2 * j];
        float q1 = st[2 * j + 1] * st[2 * j + 1];
        e_[j] = q0 + q1;
        d_[j] = q0 - q1;
    }
    float z3 = ((d_[0] + d_[1]) + (d_[2] + d_[3])) + ((d_[4] + d_[5]) + (d_[6] + d_[7]));
    float f_[4], g_[4];
    #pragma unroll
    for (int m = 0; m < 4; m++) {
        f_[m] = e_[2 * m] + e_[2 * m + 1];
        g_[m] = e_[2 * m] - e_[2 * m + 1];
    }
    float z2 = (g_[0] + g_[1]) + (g_[2] + g_[3]);
    float z1 = (f_[0] - f_[1]) + (f_[2] - f_[3]);
    float z0 = (f_[0] + f_[1]) - (f_[2] + f_[3]);
    float zq[NQ] = {z0, z1, z2, z3};

    float z[NQ];
    #pragma unroll
    for (int q = 0; q < NQ; q++) {
        const int mask = 1 << (3 - q);
        float acc = 0.f;
        #pragma unroll
        for (int idx = 0; idx < DIM; idx++)
            if ((idx & mask) == 0)
                acc = fmaf(st[idx], st[idx | mask], acc);
        z[q] = fmaf(czw[q], zq[q], nxw[q] * acc);
    }

    // ---- linear head + softmax (logits bounded; skip max-subtraction)
    float l[6];
    #pragma unroll
    for (int k = 0; k < 6; k++) {
        float acc = bs[k];
        #pragma unroll
        for (int q = 0; q < NQ; q++) acc = fmaf(Ws[k * 4 + q], z[q], acc);
        l[k] = acc;
    }
    float eo[6], ssum = 0.f;
    #pragma unroll
    for (int k = 0; k < 6; k++) { eo[k] = __expf(l[k]); ssum += eo[k]; }
    float inv = __frcp_rn(ssum);

    out[i * 3 + 0] = make_float2(eo[0] * inv, eo[1] * inv);
    out[i * 3 + 1] = make_float2(eo[2] * inv, eo[3] * inv);
    out[i * 3 + 2] = make_float2(eo[4] * inv, eo[5] * inv);
}

extern "C" void kernel_launch(void* const* d_in, const int* in_sizes, int n_in,
                              void* d_out, int out_size) {
    const float4* x  = (const float4*)d_in[0];
    const float*  qw = (const float*)d_in[1];
    const float*  W  = (const float*)d_in[2];
    const float*  b  = (const float*)d_in[3];
    float2* out = (float2*)d_out;
    int B = in_sizes[0] / 4;
    int threads = 256;
    int blocks = (B + threads - 1) / threads;
    qnn_kernel<<<blocks, threads>>>(x, qw, W, b, out, B);
}

// round 4
// speedup vs baseline: 1.6441x; 1.0025x over previous
#include <cuda_runtime.h>

// QNN: 4-qubit RY/CNOT circuit + linear head + softmax. One sample per thread.
// Algebraic folds: layer-0 RYs merged into encoding angles (RY(a)RY(b)=RY(a+b));
// layer-2 RYs merged into Z-readout via R(t)^T Z R(t) = cos(t) Z - sin(t) X.
// Inputs: x [B,4] f32, quantum_weights [3,4] f32, W [6,4] f32, b [6] f32.
// Output: softmax probs [B,6] f32.

#define NQ 4
#define DIM 16

__global__ __launch_bounds__(256) void qnn_kernel(
    const float4* __restrict__ x,     // [B] rows of 4 angles
    const float*  __restrict__ qw,    // [12] trainable angles (3 layers x 4 qubits)
    const float*  __restrict__ W,     // [24] = [6,4]
    const float*  __restrict__ bias,  // [6]
    float2*       __restrict__ out,   // [B*3] (== [B,6] f32)
    int B)
{
    __shared__ float hw0[4];          // 0.5 * layer0 angle (folded into encoding)
    __shared__ float c1w[4], s1w[4];  // cos/sin of layer1 half-angles
    __shared__ float czw[4], nxw[4];  // cos(theta2), -2*sin(theta2) (full angle!)
    __shared__ float Ws[24], bs[6];

    int t = threadIdx.x;
    if (t < 4) {
        hw0[t] = 0.5f * qw[t];
        float s, c;
        __sincosf(0.5f * qw[4 + t], &s, &c);
        c1w[t] = c; s1w[t] = s;
        float s2, c2;
        __sincosf(qw[8 + t], &s2, &c2);     // FULL angle for the observable fold
        czw[t] = c2; nxw[t] = -2.0f * s2;
    }
    if (t < 24) Ws[t] = W[t];
    if (t < 6)  bs[t] = bias[t];
    __syncthreads();

    int i = blockIdx.x * 256 + t;
    if (i >= B) return;

    // ---- encoding + layer0: |psi> = prod_q RY(x_q + w0_q)|0>
    float4 xv = x[i];
    float ca[4], sa[4];
    __sincosf(fmaf(0.5f, xv.x, hw0[0]), &sa[0], &ca[0]);
    __sincosf(fmaf(0.5f, xv.y, hw0[1]), &sa[1], &ca[1]);
    __sincosf(fmaf(0.5f, xv.z, hw0[2]), &sa[2], &ca[2]);
    __sincosf(fmaf(0.5f, xv.w, hw0[3]), &sa[3], &ca[3]);

    // index bit for qubit q is (idx >> (3-q)) & 1 (wire 0 most significant)
    float p01[4], p23[4];
    p01[0] = ca[0] * ca[1]; p01[1] = ca[0] * sa[1];
    p01[2] = sa[0] * ca[1]; p01[3] = sa[0] * sa[1];
    p23[0] = ca[2] * ca[3]; p23[1] = ca[2] * sa[3];
    p23[2] = sa[2] * ca[3]; p23[3] = sa[2] * sa[3];

    float st[DIM];
    #pragma unroll
    for (int a = 0; a < 4; a++)
        #pragma unroll
        for (int d = 0; d < 4; d++)
            st[a * 4 + d] = p01[a] * p23[d];

    // ---- ring CNOTs #1 (register permutation, free)
    #pragma unroll
    for (int e = 0; e < NQ; e++) {
        const int mc = 1 << (3 - e);
        const int mt = 1 << (3 - ((e + 1) & 3));
        #pragma unroll
        for (int idx = 0; idx < DIM; idx++) {
            if ((idx & mc) && !(idx & mt)) {
                float tmp = st[idx]; st[idx] = st[idx | mt]; st[idx | mt] = tmp;
            }
        }
    }

    // ---- layer 1 trainable RYs (the only remaining butterfly layer)
    #pragma unroll
    for (int q = 0; q < NQ; q++) {
        float cc = c1w[q], ss = s1w[q];
        const int mask = 1 << (3 - q);
        #pragma unroll
        for (int idx = 0; idx < DIM; idx++) {
            if ((idx & mask) == 0) {
                float a0 = st[idx];
                float a1 = st[idx | mask];
                st[idx]        = fmaf(cc, a0, -ss * a1);
                st[idx | mask] = fmaf(ss, a0,  cc * a1);
            }
        }
    }

    // ---- ring CNOTs #2 (free)
    #pragma unroll
    for (int e = 0; e < NQ; e++) {
        const int mc = 1 << (3 - e);
        const int mt = 1 << (3 - ((e + 1) & 3));
        #pragma unroll
        for (int idx = 0; idx < DIM; idx++) {
            if ((idx & mc) && !(idx & mt)) {
                float tmp = st[idx]; st[idx] = st[idx | mt]; st[idx | mt] = tmp;
            }
        }
    }

    // ---- readout with layer 2 folded in:
    // z_q = cos(t_q) * <Z_q> - sin(t_q) * <X_q>,  <X_q> = 2 * sum_pairs a0*a1
    // <Z_q> via signed tree over probabilities
    float e_[8], d_[8];
    #pragma unroll
    for (int j = 0; j < 8; j++) {
        float q0 = st[2 * j] * st[2 * j];
        float q1 = st[2 * j + 1] * st[2 * j + 1];
        e_[j] = q0 + q1;
        d_[j] = q0 - q1;
    }
    float z3 = ((d_[0] + d_[1]) + (d_[2] + d_[3])) + ((d_[4] + d_[5]) + (d_[6] + d_[7]));
    float f_[4], g_[4];
    #pragma unroll
    for (int m = 0; m < 4; m++) {
        f_[m] = e_[2 * m] + e_[2 * m + 1];
        g_[m] = e_[2 * m] - e_[2 * m + 1];
    }
    float z2 = (g_[0] + g_[1]) + (g_[2] + g_[3]);
    float z1 = (f_[0] - f_[1]) + (f_[2] - f_[3]);
    float z0 = (f_[0] + f_[1]) - (f_[2] + f_[3]);
    float zq[NQ] = {z0, z1, z2, z3};

    float z[NQ];
    #pragma unroll
    for (int q = 0; q < NQ; q++) {
        const int mask = 1 << (3 - q);
        float acc = 0.f;
        #pragma unroll
        for (int idx = 0; idx < DIM; idx++)
            if ((idx & mask) == 0)
                acc = fmaf(st[idx], st[idx | mask], acc);
        z[q] = fmaf(czw[q], zq[q], nxw[q] * acc);
    }

    // ---- linear head + softmax (logits bounded; skip max-subtraction)
    float l[6];
    #pragma unroll
    for (int k = 0; k < 6; k++) {
        float acc = bs[k];
        #pragma unroll
        for (int q = 0; q < NQ; q++) acc = fmaf(Ws[k * 4 + q], z[q], acc);
        l[k] = acc;
    }
    float eo[6], ssum = 0.f;
    #pragma unroll
    for (int k = 0; k < 6; k++) { eo[k] = __expf(l[k]); ssum += eo[k]; }
    float inv = __frcp_rn(ssum);

    out[i * 3 + 0] = make_float2(eo[0] * inv, eo[1] * inv);
    out[i * 3 + 1] = make_float2(eo[2] * inv, eo[3] * inv);
    out[i * 3 + 2] = make_float2(eo[4] * inv, eo[5] * inv);
}

extern "C" void kernel_launch(void* const* d_in, const int* in_sizes, int n_in,
                              void* d_out, int out_size) {
    const float4* x  = (const float4*)d_in[0];
    const float*  qw = (const float*)d_in[1];
    const float*  W  = (const float*)d_in[2];
    const float*  b  = (const float*)d_in[3];
    float2* out = (float2*)d_out;
    int B = in_sizes[0] / 4;
    int threads = 256;
    int blocks = (B + threads - 1) / threads;
    qnn_kernel<<<blocks, threads>>>(x, qw, W, b, out, B);
}

// round 6
// speedup vs baseline: 1.9582x; 1.1910x over previous
#include <cuda_runtime.h>

// QNN via Heisenberg-picture Pauli propagation (corrected z2).
// Circuit: enc(x+w0) -> P(ring CNOTs) -> RY(w1) -> P -> RY(w2) -> measure Z_q.
// z_q = sum of 30 monomials in C_j=cos(x_j+w0_j), S_j=sin(x_j+w0_j) with
// batch-uniform coefficients from w1 (c_j,s_j full-angle) and w2 (u_q,v_q).
// Derivation verified via basis-state checks of the CNOT conjugation map and
// full phase-tracked Pauli reduction.
// Inputs: x [B,4] f32, quantum_weights [3,4] f32, W [6,4] f32, b [6] f32.
// Output: softmax probs [B,6] f32.

__global__ __launch_bounds__(256) void qnn_kernel(
    const float4* __restrict__ x,     // [B] rows of 4 angles
    const float*  __restrict__ qw,    // [12] trainable angles
    const float*  __restrict__ W,     // [24] = [6,4]
    const float*  __restrict__ bias,  // [6]
    float2*       __restrict__ out,   // [B*3] (== [B,6] f32)
    int B)
{
    __shared__ float w0s[4];
    __shared__ float trig[16];            // c0..3,s0..3 (w1 full); u0..3,v0..3 (w2 full)
    __shared__ float A0[6], A1[5], A2[6], A3[13];
    __shared__ float Ws[24], bs[6];

    int t = threadIdx.x;
    if (t < 4) {
        w0s[t] = qw[t];
        float s, c;
        __sincosf(qw[4 + t], &s, &c); trig[t] = c;     trig[4 + t]  = s;
        __sincosf(qw[8 + t], &s, &c); trig[8 + t] = c; trig[12 + t] = s;
    }
    if (t < 24) Ws[t] = W[t];
    if (t < 6)  bs[t] = bias[t];
    __syncthreads();

    if (t == 0) {
        float c0 = trig[0], c1 = trig[1], c2 = trig[2], c3 = trig[3];
        float s0 = trig[4], s1 = trig[5], s2 = trig[6], s3 = trig[7];
        float u0 = trig[8], u1 = trig[9], u2 = trig[10], u3 = trig[11];
        float v0 = trig[12], v1 = trig[13], v2 = trig[14], v3 = trig[15];

        // z0: C0C1C3, S0S1C2S3, S1S2C3, S0, C0C2C3, S0S2
        A0[0] =  u0 * c1 * c2 * c3;
        A0[1] = -u0 * c1 * c2 * s3;
        A0[2] = -u0 * s1 * c2 * c3;
        A0[3] = -u0 * s1 * s2 * s3;
        A0[4] = -v0 * s0 * s1;          // * C0C2C3
        A0[5] = -v0 * c0 * c1;          // * S0S2
        // z1: C0C2C3, S0S2, C2, C0C1S2S3, S1S3
        A1[0] =  u1 * c0 * c1;
        A1[1] =  u1 * s0 * s1;
        A1[2] = -v1 * s1 * s2;          // * C2
        A1[3] = -v1 * s1 * c2;          // * C0C1S2S3
        A1[4] = -v1 * c1 * c2;          // * S1S3
        // z2: C1C3, C0S1S2C3, S0S1C2, S0S3, C3, S0S1S2
        A2[0] =  u2 * c0 * c1 * c2;     // * C1C3
        A2[1] = -u2 * c0 * s1 * c2;     // * C0S1S2C3   (the term R5 missed)
        A2[2] = -u2 * s0 * c1 * c2;     // * S0S1C2
        A2[3] = -u2 * s0 * s1 * s2;     // * S0S3
        A2[4] = -v2 * s2 * s3;          // * C3
        A2[5] = -v2 * c2 * c3;          // * S0S1S2
        // z3: C0C2, C1S2S3, C0S1S3, S0C1C2C3, C2S3, C0C1S2, S0S2C3, S1,
        //     S1S2S3, C0C1S3, S0S1C2C3, C0S1S2, C1
        A3[0]  =  u3 * c0 * c1 * c2 * c3;  // * C0C2
        A3[1]  = -u3 * c0 * c1 * s2 * c3;  // * C1S2S3
        A3[2]  =  u3 * c0 * s1 * s2 * c3;  // * C0S1S3
        A3[3]  = -u3 * c0 * s1 * s2 * s3;  // * S0C1C2C3
        A3[4]  =  u3 * s0 * c1 * c2 * s3;  // * C2S3
        A3[5]  = -u3 * s0 * c1 * s2 * s3;  // * C0C1S2
        A3[6]  =  u3 * s0 * s1 * c2 * c3;  // * S0S2C3
        A3[7]  =  u3 * s0 * s1 * s2 * s3;  // * S1
        A3[8]  = -v3 * c0 * c1 * c3;       // * S1S2S3
        A3[9]  = -v3 * c0 * s1 * c3;       // * C0C1S3
        A3[10] = -v3 * c0 * s1 * s3;       // * S0S1C2C3
        A3[11] = -v3 * s0 * c1 * s3;       // * C0S1S2
        A3[12] = -v3 * s0 * s1 * s3;       // * C1
    }
    __syncthreads();

    int i = blockIdx.x * 256 + t;
    if (i >= B) return;

    float4 xv = x[i];
    float C0, S0, C1, S1, C2, S2, C3, S3;
    __sincosf(xv.x + w0s[0], &S0, &C0);
    __sincosf(xv.y + w0s[1], &S1, &C1);
    __sincosf(xv.z + w0s[2], &S2, &C2);
    __sincosf(xv.w + w0s[3], &S3, &C3);

    // shared pair products
    float pc01 = C0 * C1, pc23 = C2 * C3, pc02 = C0 * C2, pc13 = C1 * C3;
    float ps01 = S0 * S1, ps23 = S2 * S3, ps02 = S0 * S2, ps13 = S1 * S3;
    float ps12 = S1 * S2, ps03 = S0 * S3, pcs23 = C2 * S3;
    float c0c2c3 = C0 * pc23;
    float c0s1s2 = C0 * ps12;

    float z0 = A0[0] * (pc01 * C3);
    z0 = fmaf(A0[1], ps01 * pcs23, z0);
    z0 = fmaf(A0[2], ps12 * C3, z0);
    z0 = fmaf(A0[3], S0, z0);
    z0 = fmaf(A0[4], c0c2c3, z0);
    z0 = fmaf(A0[5], ps02, z0);

    float z1 = A1[0] * c0c2c3;
    z1 = fmaf(A1[1], ps02, z1);
    z1 = fmaf(A1[2], C2, z1);
    z1 = fmaf(A1[3], pc01 * ps23, z1);
    z1 = fmaf(A1[4], ps13, z1);

    float z2 = A2[0] * pc13;
    z2 = fmaf(A2[1], c0s1s2 * C3, z2);
    z2 = fmaf(A2[2], ps01 * C2, z2);
    z2 = fmaf(A2[3], ps03, z2);
    z2 = fmaf(A2[4], C3, z2);
    z2 = fmaf(A2[5], ps01 * S2, z2);

    float z3 = A3[0] * pc02;
    z3 = fmaf(A3[1],  C1 * ps23, z3);
    z3 = fmaf(A3[2],  C0 * ps13, z3);
    z3 = fmaf(A3[3],  S0 * (C1 * pc23), z3);
    z3 = fmaf(A3[4],  pcs23, z3);
    z3 = fmaf(A3[5],  pc01 * S2, z3);
    z3 = fmaf(A3[6],  ps02 * C3, z3);
    z3 = fmaf(A3[7],  S1, z3);
    z3 = fmaf(A3[8],  S1 * ps23, z3);
    z3 = fmaf(A3[9],  pc01 * S3, z3);
    z3 = fmaf(A3[10], ps01 * pc23, z3);
    z3 = fmaf(A3[11], c0s1s2, z3);
    z3 = fmaf(A3[12], C1, z3);

    float zq[4] = {z0, z1, z2, z3};

    // linear head + softmax (logits bounded; skip max-subtraction)
    float l[6];
    #pragma unroll
    for (int k = 0; k < 6; k++) {
        float acc = bs[k];
        #pragma unroll
        for (int q = 0; q < 4; q++) acc = fmaf(Ws[k * 4 + q], zq[q], acc);
        l[k] = acc;
    }
    float eo[6], ssum = 0.f;
    #pragma unroll
    for (int k = 0; k < 6; k++) { eo[k] = __expf(l[k]); ssum += eo[k]; }
    float inv = __frcp_rn(ssum);

    out[i * 3 + 0] = make_float2(eo[0] * inv, eo[1] * inv);
    out[i * 3 + 1] = make_float2(eo[2] * inv, eo[3] * inv);
    out[i * 3 + 2] = make_float2(eo[4] * inv, eo[5] * inv);
}

extern "C" void kernel_launch(void* const* d_in, const int* in_sizes, int n_in,
                              void* d_out, int out_size) {
    const float4* x  = (const float4*)d_in[0];
    const float*  qw = (const float*)d_in[1];
    const float*  W  = (const float*)d_in[2];
    const float*  b  = (const float*)d_in[3];
    float2* out = (float2*)d_out;
    int B = in_sizes[0] / 4;
    int threads = 256;
    int blocks = (B + threads - 1) / threads;
    qnn_kernel<<<blocks, threads>>>(x, qw, W, b, out, B);
}